// round 16
// baseline (speedup 1.0000x reference)
#include <cuda_runtime.h>
#include <cstdint>
#include <cstddef>

// Problem constants (fixed by setup_inputs: d=256, L=8, per=8192, deg=8)
#define D        256
#define PER      8192
#define NNODES   65536
#define DEG      8
#define EPL      65536
#define NLVL     7
#define NCTA     148                // total CTAs (one per SM)
#define NCOMP    128                // compute CTAs: 64 rows each = 8192
#define NTHR     512                // compute threads per compute CTA (16 warps)
#define CWARPS   4                  // LDG copy warps inside each compute CTA
#define NTHR_TOT (NTHR + CWARPS * 32)   // 640
#define WARPS_TOT (NTHR_TOT / 32)   // 20 warps in pure-copy CTAs
#define TMA_WARPS_PER_CTA 4         // TMA streams per pure-copy CTA
#define NTMA ((NCTA - NCOMP) * TMA_WARPS_PER_CTA)            // 80 TMA streams
#define TOTAL_LDG (NCOMP * CWARPS + (NCTA - NCOMP) * (WARPS_TOT - TMA_WARPS_PER_CTA)) // 832

// TMA chunking: 16 KB chunks (1024 float4)
#define CHUNK_F4 1024
#define CHUNK_B  16384

// dynamic smem: compute CTAs: As 64x256 f32 (64KB) + Bs 2x256x32 f32 (64KB)
//               pure-copy CTAs: 4 warps x 2 x 16KB staging = 128KB
#define AS_BYTES (64 * 256 * 4)
#define BS_BYTES (2 * 256 * 32 * 4)
#define DYN_SMEM (AS_BYTES + BS_BYTES)

// named barrier for the 512 compute threads only (copy warps never join)
#define CBAR() asm volatile("bar.sync 1, %0;" :: "n"(NTHR) : "memory")

// ---------------- device scratch (no allocation allowed) ----------------
__device__ float  g_Ha[PER * D];         // H ping
__device__ float  g_Hb[PER * D];         // H pong
__device__ float  g_y[PER * D];          // y = x + x2 for last-layer rows
__device__ float  g_asrc2[2][PER];       // ping-pong a_src
__device__ float  g_adst[PER];
__device__ double g_psum[NCOMP];         // per-CTA LN partials (no atomics)
__device__ double g_psq[NCOMP];
__device__ int    g_count = 0;           // grid barrier state
__device__ int    g_sense = 0;

__device__ __forceinline__ void cp16(uint32_t dst, const float* src) {
    asm volatile("cp.async.cg.shared.global [%0], [%1], 16;\n" :: "r"(dst), "l"(src));
}

__device__ __forceinline__ void mma_tf32(float* c, const uint32_t* a, const uint32_t* b) {
    asm volatile(
        "mma.sync.aligned.m16n8k8.row.col.f32.tf32.tf32.f32 "
        "{%0,%1,%2,%3}, {%4,%5,%6,%7}, {%8,%9}, {%0,%1,%2,%3};\n"
        : "+f"(c[0]), "+f"(c[1]), "+f"(c[2]), "+f"(c[3])
        : "r"(a[0]), "r"(a[1]), "r"(a[2]), "r"(a[3]), "r"(b[0]), "r"(b[1]));
}

// grid-wide barrier over compute warps of the NCOMP compute CTAs
__device__ __forceinline__ void gbar(int& ls) {
    CBAR();
    if (threadIdx.x == 0) {
        __threadfence();
        if (atomicAdd(&g_count, 1) == NCOMP - 1) {
            g_count = 0;
            __threadfence();
            atomicExch(&g_sense, ls);
        } else {
            while (*(volatile int*)&g_sense != ls) __nanosleep(64);
            __threadfence();
        }
    }
    CBAR();
    ls ^= 1;
}

// ---------------- LDG copy worker: batch-8 register pipeline -----------------
// Covers region [base, ec4) with TOTAL_LDG interleaved warps.
__device__ __forceinline__ void copy_work_ldg(const float4* __restrict__ esrc,
                                              float4* __restrict__ edst,
                                              long long base, long long ec4,
                                              long long gw)
{
    const int lane = threadIdx.x & 31;
    const long long stride = (long long)TOTAL_LDG * 32;
    long long i = base + gw * 32 + lane;
    float4 v[8];
    for (; i + 7 * stride < ec4; i += 8 * stride) {
#pragma unroll
        for (int u = 0; u < 8; u++) v[u] = __ldcs(&esrc[i + u * stride]);
#pragma unroll
        for (int u = 0; u < 8; u++) __stcs(&edst[i + u * stride], v[u]);
    }
    for (; i < ec4; i += stride) __stcs(&edst[i], __ldcs(&esrc[i]));
}

// ---------------- TMA bulk copy stream (lane0 of a copy warp) ----------------
// Double-buffered 16KB chunks: gmem -> smem (mbarrier complete_tx) -> gmem
// (bulk_group). wait_group.read frees the smem buffer as soon as the store
// has READ it, so loads pipeline without waiting store completion.
__device__ __forceinline__ void mbar_wait_parity(uint32_t mb, uint32_t ph) {
    uint32_t done;
    do {
        asm volatile(
            "{\n\t.reg .pred p;\n\t"
            "mbarrier.try_wait.parity.acquire.cta.shared::cta.b64 p, [%1], %2, 0x989680;\n\t"
            "selp.b32 %0, 1, 0, p;\n\t}"
            : "=r"(done) : "r"(mb), "r"(ph) : "memory");
    } while (!done);
}

__device__ __forceinline__ void copy_work_tma(const float4* __restrict__ esrc,
                                              float4* __restrict__ edst,
                                              long long nchunks, long long s,
                                              uint32_t sbuf, uint32_t mb)
{
    // init my two mbarriers (same thread inits and uses them)
    asm volatile("mbarrier.init.shared.b64 [%0], 1;" :: "r"(mb) : "memory");
    asm volatile("mbarrier.init.shared.b64 [%0], 1;" :: "r"(mb + 8) : "memory");
    asm volatile("fence.proxy.async.shared::cta;" ::: "memory");

    const long long step = NTMA;
    uint32_t ph[2] = {0, 0};

    auto bulk_ld = [&](int k, long long chunk) {
        uint32_t m = mb + k * 8;
        asm volatile("mbarrier.arrive.expect_tx.shared.b64 _, [%0], %1;"
                     :: "r"(m), "r"((uint32_t)CHUNK_B) : "memory");
        asm volatile(
            "cp.async.bulk.shared::cta.global.mbarrier::complete_tx::bytes [%0], [%1], %2, [%3];"
            :: "r"(sbuf + (uint32_t)k * CHUNK_B),
               "l"((const void*)(esrc + chunk * CHUNK_F4)),
               "r"((uint32_t)CHUNK_B), "r"(m) : "memory");
    };

    // prologue: fill both buffers
    if (s < nchunks)            bulk_ld(0, s);
    if (s + step < nchunks)     bulk_ld(1, s + step);

    long long c = s;
    int i = 0;
    for (; c < nchunks; c += step, i++) {
        int k = i & 1;
        mbar_wait_parity(mb + k * 8, ph[k]);
        ph[k] ^= 1;
        asm volatile(
            "cp.async.bulk.global.shared::cta.bulk_group [%0], [%1], %2;"
            :: "l"((void*)(edst + c * CHUNK_F4)),
               "r"(sbuf + (uint32_t)k * CHUNK_B),
               "r"((uint32_t)CHUNK_B) : "memory");
        asm volatile("cp.async.bulk.commit_group;" ::: "memory");
        long long nc = c + 2 * step;
        if (nc < nchunks) {
            // free buffer k: wait until all committed stores have READ smem
            asm volatile("cp.async.bulk.wait_group.read 0;" ::: "memory");
            bulk_ld(k, nc);
        }
    }
    asm volatile("cp.async.bulk.wait_group 0;" ::: "memory");  // stores complete
}

// ---------------- GEMM from smem As: Hout[64 x 256] = As @ W^T ----------------
__device__ __forceinline__ void gemm_from_smem(float* As, float* Bs,
                                               const float* __restrict__ W,
                                               float* __restrict__ Hout,
                                               int cta, int tid)
{
    const int warp = tid >> 5, lane = tid & 31;
    const int wm = (warp & 3) * 16;
    const int wn = (warp >> 2) * 64;
    const uint32_t as_base = (uint32_t)__cvta_generic_to_shared(As);
    const uint32_t bs_base = (uint32_t)__cvta_generic_to_shared(Bs);

    float acc[8][4];
#pragma unroll
    for (int i = 0; i < 8; i++)
#pragma unroll
        for (int j = 0; j < 4; j++) acc[i][j] = 0.f;

    auto stageB = [&](int buf, int c) {
#pragma unroll
        for (int i = 0; i < 4; i++) {
            int f = tid + i * NTHR;
            int r = f >> 3, sg = f & 7;
            const float* src = W + (size_t)r * D + c * 32 + sg * 4;
            uint32_t dst = bs_base + (uint32_t)(((buf * 256 + r) * 8 + (sg ^ (r & 7))) * 16);
            cp16(dst, src);
        }
        asm volatile("cp.async.commit_group;\n" ::: "memory");
    };

    stageB(0, 0);
#pragma unroll 1
    for (int c = 0; c < 8; c++) {
        if (c + 1 < 8) {
            stageB((c + 1) & 1, c + 1);
            asm volatile("cp.async.wait_group 1;\n" ::: "memory");
        } else {
            asm volatile("cp.async.wait_group 0;\n" ::: "memory");
        }
        CBAR();
        const int buf = c & 1;
#pragma unroll
        for (int kk = 0; kk < 4; kk++) {
            uint32_t a[4], b[8][2];
            {
                int arow = wm + (lane & 7) + ((lane & 8) ? 8 : 0);
                int seg  = c * 8 + kk * 2 + ((lane >> 4) & 1);
                int sw   = (seg & ~7) | ((seg ^ arow) & 7);
                uint32_t aaddr = as_base + (uint32_t)((arow * 64 + sw) * 16);
                asm volatile("ldmatrix.sync.aligned.m8n8.x4.shared.b16 {%0,%1,%2,%3}, [%4];\n"
                             : "=r"(a[0]), "=r"(a[1]), "=r"(a[2]), "=r"(a[3]) : "r"(aaddr));
            }
#pragma unroll
            for (int jp = 0; jp < 4; jp++) {
                int brow = wn + jp * 16 + (lane & 7) + ((lane & 16) ? 8 : 0);
                int bsg  = (kk * 2 + ((lane >> 3) & 1)) ^ (brow & 7);
                uint32_t baddr = bs_base + (uint32_t)(((buf * 256 + brow) * 8 + bsg) * 16);
                asm volatile("ldmatrix.sync.aligned.m8n8.x4.shared.b16 {%0,%1,%2,%3}, [%4];\n"
                             : "=r"(b[jp * 2][0]), "=r"(b[jp * 2][1]),
                               "=r"(b[jp * 2 + 1][0]), "=r"(b[jp * 2 + 1][1])
                             : "r"(baddr));
            }
#pragma unroll
            for (int nt = 0; nt < 8; nt++) mma_tf32(acc[nt], a, b[nt]);
        }
        CBAR();
    }
    int row0 = cta * 64 + wm + (lane >> 2);
#pragma unroll
    for (int nt = 0; nt < 8; nt++) {
        int col = wn + nt * 8 + (lane & 3) * 2;
        *reinterpret_cast<float2*>(&Hout[(size_t)row0 * D + col]) =
            make_float2(acc[nt][0], acc[nt][1]);
        *reinterpret_cast<float2*>(&Hout[(size_t)(row0 + 8) * D + col]) =
            make_float2(acc[nt][2], acc[nt][3]);
    }
}

// ---------------- aggregate level l into smem As (or y for last level) -------
__device__ __forceinline__ void agg_to_smem(const int* __restrict__ ei,
                                            const float* __restrict__ bias,
                                            const float* __restrict__ x,
                                            const float* __restrict__ Hin,
                                            float* As, int l, const float* s_vsrc,
                                            float* red, int cta, int tid)
{
    const int warp = tid >> 5, lane = tid & 31;
    const float* asrc = g_asrc2[l & 1];
    float* anext = g_asrc2[(l + 1) & 1];
    const float4* H4 = (const float4*)Hin;
    const float4* b4 = (const float4*)bias;
    float ts = 0.f, tq = 0.f;
    const int lastlvl = (l == NLVL);

#pragma unroll 1
    for (int k = 0; k < 4; k++) {
        const int lr  = warp + k * 16;
        const int row = cta * 64 + lr;
        const int eb = (l - 1) * EPL + row * DEG;
        int sj[DEG]; float p[DEG];
        float ad = (l == 1) ? g_adst[row] : 0.f;
        float m = -1e30f;
#pragma unroll
        for (int j = 0; j < DEG; j++) {
            int s = ei[eb + j] - (l - 1) * PER;
            sj[j] = s;
            float a = asrc[s] + ad;
            a = a > 0.f ? a : 0.2f * a;           // leaky_relu 0.2
            p[j] = a;
            m = fmaxf(m, a);
        }
        float den = 0.f;
#pragma unroll
        for (int j = 0; j < DEG; j++) { p[j] = __expf(p[j] - m); den += p[j]; }
        float inv = 1.f / den;
#pragma unroll
        for (int j = 0; j < DEG; j++) p[j] *= inv;

        float4 a0 = b4[lane], a1 = b4[32 + lane];
#pragma unroll
        for (int j = 0; j < DEG; j++) {
            float4 h0 = H4[(size_t)sj[j] * 64 + lane];
            float4 h1 = H4[(size_t)sj[j] * 64 + 32 + lane];
            a0.x = fmaf(p[j], h0.x, a0.x); a0.y = fmaf(p[j], h0.y, a0.y);
            a0.z = fmaf(p[j], h0.z, a0.z); a0.w = fmaf(p[j], h0.w, a0.w);
            a1.x = fmaf(p[j], h1.x, a1.x); a1.y = fmaf(p[j], h1.y, a1.y);
            a1.z = fmaf(p[j], h1.z, a1.z); a1.w = fmaf(p[j], h1.w, a1.w);
        }
        if (!lastlvl) {
            int sw0 = (lane & ~7) | ((lane ^ lr) & 7);
            ((float4*)As)[lr * 64 + sw0]      = a0;
            ((float4*)As)[lr * 64 + 32 + sw0] = a1;
            const float4* v4 = (const float4*)s_vsrc;
            float4 v0 = v4[lane], v1 = v4[32 + lane];
            float d = a0.x * v0.x + a0.y * v0.y + a0.z * v0.z + a0.w * v0.w
                    + a1.x * v1.x + a1.y * v1.y + a1.z * v1.z + a1.w * v1.w;
#pragma unroll
            for (int o = 16; o > 0; o >>= 1) d += __shfl_xor_sync(0xffffffffu, d, o);
            if (lane == 0) anext[row] = d;
        } else {
            float4 x0 = ((const float4*)x)[(size_t)(7 * PER + row) * 64 + lane];
            float4 x1 = ((const float4*)x)[(size_t)(7 * PER + row) * 64 + 32 + lane];
            a0.x += x0.x; a0.y += x0.y; a0.z += x0.z; a0.w += x0.w;
            a1.x += x1.x; a1.y += x1.y; a1.z += x1.z; a1.w += x1.w;
            ((float4*)g_y)[(size_t)row * 64 + lane]      = a0;
            ((float4*)g_y)[(size_t)row * 64 + 32 + lane] = a1;
            ts += a0.x + a0.y + a0.z + a0.w + a1.x + a1.y + a1.z + a1.w;
            tq += a0.x * a0.x + a0.y * a0.y + a0.z * a0.z + a0.w * a0.w
                + a1.x * a1.x + a1.y * a1.y + a1.z * a1.z + a1.w * a1.w;
        }
    }
    if (lastlvl) {
#pragma unroll
        for (int o = 16; o > 0; o >>= 1) {
            ts += __shfl_xor_sync(0xffffffffu, ts, o);
            tq += __shfl_xor_sync(0xffffffffu, tq, o);
        }
        if (lane == 0) { red[warp] = ts; red[16 + warp] = tq; }
        CBAR();
        if (tid == 0) {
            float a = 0.f, b = 0.f;
#pragma unroll
            for (int j = 0; j < 16; j++) { a += red[j]; b += red[16 + j]; }
            g_psum[cta] += (double)a;
            g_psq[cta]  += (double)b;
        }
    }
}

// ---------------- the persistent kernel --------------------------------------
__global__ void __launch_bounds__(NTHR_TOT, 1) persist_kernel(
    const float* __restrict__ x, const int* __restrict__ ei,
    const float* __restrict__ W, const float* __restrict__ att_src,
    const float* __restrict__ att_dst, const float* __restrict__ bias,
    const float* __restrict__ gamma, const float* __restrict__ beta,
    float* __restrict__ out,
    const float4* __restrict__ esrc, float4* __restrict__ edst,
    long long ec4, long long tma_chunks)
{
    __shared__ float s_vsrc[D];
    __shared__ float s_vdst[D];
    __shared__ float red[32];
    __shared__ float sbc[2];
    __shared__ uint64_t cmbar[2 * TMA_WARPS_PER_CTA];   // 2 mbarriers per TMA warp
    extern __shared__ float dyn[];
    float* As = dyn;                          // 64 x 256 (swizzled 16B segs)
    float* Bs = dyn + AS_BYTES / 4;           // 2 x 256 x 32 (swizzled)

    const int cta = blockIdx.x;
    const int tid = threadIdx.x;
    const int warp = tid >> 5, lane = tid & 31;
    const long long ldg_base = tma_chunks * CHUNK_F4;   // LDG region start

    // ===== pure-copy CTAs (20 SMs): warps 0-3 TMA, warps 4-19 LDG =============
    if (cta >= NCOMP) {
        if (esrc != nullptr) {
            if (warp < TMA_WARPS_PER_CTA) {
                if (lane == 0) {
                    uint32_t sbuf = (uint32_t)__cvta_generic_to_shared(dyn)
                                  + (uint32_t)warp * (2 * CHUNK_B);
                    uint32_t mb = (uint32_t)__cvta_generic_to_shared(&cmbar[warp * 2]);
                    long long s = (long long)(cta - NCOMP) * TMA_WARPS_PER_CTA + warp;
                    copy_work_tma(esrc, edst, tma_chunks, s, sbuf, mb);
                }
            } else {
                long long gw = (long long)NCOMP * CWARPS
                             + (long long)(cta - NCOMP) * (WARPS_TOT - TMA_WARPS_PER_CTA)
                             + (warp - TMA_WARPS_PER_CTA);
                copy_work_ldg(esrc, edst, ldg_base, ec4, gw);
            }
        }
        return;
    }

    // ===== LDG copy warps inside compute CTAs =================================
    if (tid >= NTHR) {
        if (esrc != nullptr) {
            long long gw = (long long)cta * CWARPS + ((tid - NTHR) >> 5);
            copy_work_ldg(esrc, edst, ldg_base, ec4, gw);
        }
        return;
    }

    // ===== compute warps =======================================================
    int ls = 1 ^ *((volatile int*)&g_sense);

    // P0: v-vectors (per-CTA smem), rowdots, stats over x head
    if (tid < D) {
        float s = 0.f, t = 0.f;
        for (int k = 0; k < D; k++) {
            float w2 = W[k * D + tid];
            s = fmaf(w2, att_src[k], s);
            t = fmaf(w2, att_dst[k], t);
        }
        s_vsrc[tid] = s;
        s_vdst[tid] = t;
    }
    CBAR();

    for (int idx = cta * 16 + warp; idx < 2 * PER; idx += NCOMP * 16) {
        const float* A; const float* v; int r;
        if (idx < PER) { r = idx;       A = x;                    v = s_vsrc; }
        else           { r = idx - PER; A = x + (size_t)PER * D;  v = s_vdst; }
        const float4* a4 = (const float4*)(A + (size_t)r * D);
        const float4* v4 = (const float4*)v;
        float s = 0.f;
#pragma unroll
        for (int i = 0; i < 2; i++) {
            float4 a  = a4[i * 32 + lane];
            float4 vv = v4[i * 32 + lane];
            s += a.x * vv.x + a.y * vv.y + a.z * vv.z + a.w * vv.w;
        }
#pragma unroll
        for (int o = 16; o > 0; o >>= 1) s += __shfl_xor_sync(0xffffffffu, s, o);
        if (lane == 0) { if (idx < PER) g_asrc2[1][r] = s; else g_adst[r] = s; }
    }

    {
        float s = 0.f, q = 0.f;
        const float4* x4 = (const float4*)x;
        const int total4 = (NNODES - PER) * (D / 4);
        for (int i = cta * NTHR + tid; i < total4; i += NCOMP * NTHR) {
            float4 v = x4[i];
            s += v.x + v.y + v.z + v.w;
            q += v.x * v.x + v.y * v.y + v.z * v.z + v.w * v.w;
        }
#pragma unroll
        for (int o = 16; o > 0; o >>= 1) {
            s += __shfl_xor_sync(0xffffffffu, s, o);
            q += __shfl_xor_sync(0xffffffffu, q, o);
        }
        if (lane == 0) { red[warp] = s; red[16 + warp] = q; }
        CBAR();
        if (tid == 0) {
            float a = 0.f, b = 0.f;
#pragma unroll
            for (int j = 0; j < 16; j++) { a += red[j]; b += red[16 + j]; }
            g_psum[cta] = (double)a;     // overwrite: no zero-init needed
            g_psq[cta]  = (double)b;
        }
    }

    // ===== level-1 GEMM: As <- x[layer0] rows (this CTA's 64), gemm -> Ha =====
    {
#pragma unroll
        for (int k = 0; k < 4; k++) {
            int lr = warp + k * 16;
            const float4* xr = (const float4*)(x + (size_t)(cta * 64 + lr) * D);
            float4 a0 = xr[lane], a1 = xr[32 + lane];
            int sw0 = (lane & ~7) | ((lane ^ lr) & 7);
            ((float4*)As)[lr * 64 + sw0]      = a0;
            ((float4*)As)[lr * 64 + 32 + sw0] = a1;
        }
        CBAR();
        gemm_from_smem(As, Bs, W, g_Ha, cta, tid);
    }
    gbar(ls);   // H^1 complete everywhere (also covers P0 scalars)

    // ===== chain: one gbar per level ==========================================
    float* Hbuf[2];
    Hbuf[0] = g_Ha; Hbuf[1] = g_Hb;
#pragma unroll 1
    for (int l = 1; l < NLVL; l++) {
        const float* Hin = Hbuf[(l + 1) & 1];
        float* Hout = Hbuf[l & 1];
        agg_to_smem(ei, bias, x, Hin, As, l, s_vsrc, red, cta, tid);
        CBAR();                                  // As ready (CTA-local)
        gemm_from_smem(As, Bs, W, Hout, cta, tid);
        gbar(ls);                                // H^{l+1} complete everywhere
    }
    // level 7: aggregate to y + stats
    agg_to_smem(ei, bias, x, Hbuf[0], As, NLVL, s_vsrc, red, cta, tid);
    gbar(ls);   // stats complete everywhere

    // ===== norm ================================================================
    if (warp == 0) {
        double ds = 0.0, dq = 0.0;
        for (int i = lane; i < NCOMP; i += 32) { ds += g_psum[i]; dq += g_psq[i]; }
#pragma unroll
        for (int o = 16; o > 0; o >>= 1) {
            ds += __shfl_xor_sync(0xffffffffu, ds, o);
            dq += __shfl_xor_sync(0xffffffffu, dq, o);
        }
        if (lane == 0) {
            double cnt  = (double)NNODES * D;
            double mean = ds / cnt;
            double var  = dq / cnt - mean * mean;
            sbc[0] = (float)mean;
            sbc[1] = rsqrtf((float)var + 1e-5f);
        }
    }
    CBAR();
    const float mu = sbc[0], rstd = sbc[1];
    const int total4 = NNODES * (D / 4);
    const int tail4  = (NNODES - PER) * (D / 4);
    for (int i = cta * NTHR + tid; i < total4; i += NCOMP * NTHR) {
        float4 v = (i < tail4) ? ((const float4*)x)[i] : ((const float4*)g_y)[i - tail4];
        int c4 = i & 63;
        float4 g = ((const float4*)gamma)[c4];
        float4 b = ((const float4*)beta)[c4];
        float4 o;
        o.x = (v.x - mu) * rstd * g.x + b.x;
        o.y = (v.y - mu) * rstd * g.y + b.y;
        o.z = (v.z - mu) * rstd * g.z + b.z;
        o.w = (v.w - mu) * rstd * g.w + b.w;
        ((float4*)out)[i] = o;
    }
}

// ---------------- launch ----------------
extern "C" void kernel_launch(void* const* d_in, const int* in_sizes, int n_in,
                              void* d_out, int out_size) {
    const float* x       = (const float*)d_in[0];
    const int*   ei      = (const int*)d_in[1];
    const float* eattr   = (const float*)d_in[2];
    const float* W       = (const float*)d_in[5];
    const float* att_src = (const float*)d_in[6];
    const float* att_dst = (const float*)d_in[7];
    const float* bias    = (const float*)d_in[8];
    const float* gamma   = (const float*)d_in[9];
    const float* beta    = (const float*)d_in[10];
    float* out = (float*)d_out;

    static bool attr_set = false;
    if (!attr_set) {
        cudaFuncSetAttribute(persist_kernel,
                             cudaFuncAttributeMaxDynamicSharedMemorySize, DYN_SMEM);
        attr_set = true;
    }

    size_t eelems = (size_t)in_sizes[2];
    bool do_copy = ((size_t)out_size >= (size_t)NNODES * D + eelems);
    const float4* e4src = do_copy ? (const float4*)eattr : nullptr;
    float4* e4dst = do_copy ? (float4*)(out + (size_t)NNODES * D) : nullptr;
    long long ec4 = do_copy ? (long long)(eelems / 4) : 0;
    // TMA takes the first ~half, rounded down to whole 16KB chunks
    long long tma_chunks = (ec4 / 2) / CHUNK_F4;

    persist_kernel<<<NCTA, NTHR_TOT, DYN_SMEM>>>(x, ei, W, att_src, att_dst, bias,
                                                 gamma, beta, out, e4src, e4dst,
                                                 ec4, tma_chunks);
}

// round 17
// speedup vs baseline: 1.3143x; 1.3143x over previous
#include <cuda_runtime.h>
#include <cstdint>
#include <cstddef>

// Problem constants (fixed by setup_inputs: d=256, L=8, per=8192, deg=8)
#define D        256
#define PER      8192
#define NNODES   65536
#define DEG      8
#define EPL      65536
#define NLVL     7
#define NCTA     148                // total CTAs (one per SM)
#define NCOMP    128                // compute CTAs: 64 rows each = 8192
#define NTHR     512                // compute threads per compute CTA (16 warps)
#define CWARPS   4                  // copy warps inside each compute CTA
#define NTHR_TOT (NTHR + CWARPS * 32)   // 640
#define WARPS_TOT (NTHR_TOT / 32)   // 20 (pure-copy CTAs use all 20)
#define TOTAL_CW (NCOMP * CWARPS + (NCTA - NCOMP) * WARPS_TOT)   // 912 copy warps

// dynamic smem: As 64x256 f32 (64KB) + Bs 2x256x32 f32 (64KB)
#define AS_BYTES (64 * 256 * 4)
#define BS_BYTES (2 * 256 * 32 * 4)
#define DYN_SMEM (AS_BYTES + BS_BYTES)

// named barrier for the 512 compute threads only (copy warps never join)
#define CBAR() asm volatile("bar.sync 1, %0;" :: "n"(NTHR) : "memory")

// ---------------- device scratch (no allocation allowed) ----------------
__device__ float  g_Ha[PER * D];         // H ping
__device__ float  g_Hb[PER * D];         // H pong
__device__ float  g_y[PER * D];          // y = x + x2 for last-layer rows
__device__ float  g_asrc2[2][PER];       // ping-pong a_src
__device__ float  g_adst[PER];
__device__ double g_psum[NCOMP];         // per-CTA LN partials (no atomics)
__device__ double g_psq[NCOMP];
__device__ int    g_count = 0;           // grid barrier state
__device__ int    g_sense = 0;

__device__ __forceinline__ void cp16(uint32_t dst, const float* src) {
    asm volatile("cp.async.cg.shared.global [%0], [%1], 16;\n" :: "r"(dst), "l"(src));
}

__device__ __forceinline__ void mma_tf32(float* c, const uint32_t* a, const uint32_t* b) {
    asm volatile(
        "mma.sync.aligned.m16n8k8.row.col.f32.tf32.tf32.f32 "
        "{%0,%1,%2,%3}, {%4,%5,%6,%7}, {%8,%9}, {%0,%1,%2,%3};\n"
        : "+f"(c[0]), "+f"(c[1]), "+f"(c[2]), "+f"(c[3])
        : "r"(a[0]), "r"(a[1]), "r"(a[2]), "r"(a[3]), "r"(b[0]), "r"(b[1]));
}

// grid-wide barrier over compute warps of the NCOMP compute CTAs
__device__ __forceinline__ void gbar(int& ls) {
    CBAR();
    if (threadIdx.x == 0) {
        __threadfence();
        if (atomicAdd(&g_count, 1) == NCOMP - 1) {
            g_count = 0;
            __threadfence();
            atomicExch(&g_sense, ls);
        } else {
            while (*(volatile int*)&g_sense != ls) __nanosleep(64);
            __threadfence();
        }
    }
    CBAR();
    ls ^= 1;
}

// ---------------- copy worker: contiguous per-warp block, batch-8 pipeline ---
// Each warp owns a contiguous span of ~ec4/TOTAL_CW float4. A batch covers
// 256 float4 = 4KB CONTIGUOUS (32 consecutive 128B lines) for max DRAM
// row-buffer / L2-sector locality on both streams.
__device__ __forceinline__ void copy_work(const float4* __restrict__ esrc,
                                          float4* __restrict__ edst,
                                          long long ec4, long long gw)
{
    const int lane = threadIdx.x & 31;
    long long per = (ec4 + TOTAL_CW - 1) / TOTAL_CW;
    long long s = gw * per;
    long long e = s + per; if (e > ec4) e = ec4;
    long long base = s;
    float4 v[8];
    for (; base + 256 <= e; base += 256) {
#pragma unroll
        for (int u = 0; u < 8; u++) v[u] = __ldcs(&esrc[base + u * 32 + lane]);
#pragma unroll
        for (int u = 0; u < 8; u++) __stcs(&edst[base + u * 32 + lane], v[u]);
    }
    for (long long i = base + lane; i < e; i += 32) __stcs(&edst[i], __ldcs(&esrc[i]));
}

// ---------------- GEMM from smem As: Hout[64 x 256] = As @ W^T ----------------
// 16 warps, warp tile 16x64 (4m x 4n), K=256 in 8 chunks of 32 (Bs double-buf).
__device__ __forceinline__ void gemm_from_smem(float* As, float* Bs,
                                               const float* __restrict__ W,
                                               float* __restrict__ Hout,
                                               int cta, int tid)
{
    const int warp = tid >> 5, lane = tid & 31;
    const int wm = (warp & 3) * 16;          // m offset within 64
    const int wn = (warp >> 2) * 64;         // n offset within 256
    const uint32_t as_base = (uint32_t)__cvta_generic_to_shared(As);
    const uint32_t bs_base = (uint32_t)__cvta_generic_to_shared(Bs);

    float acc[8][4];
#pragma unroll
    for (int i = 0; i < 8; i++)
#pragma unroll
        for (int j = 0; j < 4; j++) acc[i][j] = 0.f;

    auto stageB = [&](int buf, int c) {
#pragma unroll
        for (int i = 0; i < 4; i++) {
            int f = tid + i * NTHR;
            int r = f >> 3, sg = f & 7;
            const float* src = W + (size_t)r * D + c * 32 + sg * 4;
            uint32_t dst = bs_base + (uint32_t)(((buf * 256 + r) * 8 + (sg ^ (r & 7))) * 16);
            cp16(dst, src);
        }
        asm volatile("cp.async.commit_group;\n" ::: "memory");
    };

    stageB(0, 0);
#pragma unroll 1
    for (int c = 0; c < 8; c++) {
        if (c + 1 < 8) {
            stageB((c + 1) & 1, c + 1);
            asm volatile("cp.async.wait_group 1;\n" ::: "memory");
        } else {
            asm volatile("cp.async.wait_group 0;\n" ::: "memory");
        }
        CBAR();
        const int buf = c & 1;
#pragma unroll
        for (int kk = 0; kk < 4; kk++) {
            uint32_t a[4], b[8][2];
            {   // A frag: rows wm..wm+15 of As, k8 = c*8+kk*2(+hi)
                int arow = wm + (lane & 7) + ((lane & 8) ? 8 : 0);
                int seg  = c * 8 + kk * 2 + ((lane >> 4) & 1);
                int sw   = (seg & ~7) | ((seg ^ arow) & 7);
                uint32_t aaddr = as_base + (uint32_t)((arow * 64 + sw) * 16);
                asm volatile("ldmatrix.sync.aligned.m8n8.x4.shared.b16 {%0,%1,%2,%3}, [%4];\n"
                             : "=r"(a[0]), "=r"(a[1]), "=r"(a[2]), "=r"(a[3]) : "r"(aaddr));
            }
#pragma unroll
            for (int jp = 0; jp < 4; jp++) {   // B frags: n = wn+jp*16 .. +16
                int brow = wn + jp * 16 + (lane & 7) + ((lane & 16) ? 8 : 0);
                int bsg  = (kk * 2 + ((lane >> 3) & 1)) ^ (brow & 7);
                uint32_t baddr = bs_base + (uint32_t)(((buf * 256 + brow) * 8 + bsg) * 16);
                asm volatile("ldmatrix.sync.aligned.m8n8.x4.shared.b16 {%0,%1,%2,%3}, [%4];\n"
                             : "=r"(b[jp * 2][0]), "=r"(b[jp * 2][1]),
                               "=r"(b[jp * 2 + 1][0]), "=r"(b[jp * 2 + 1][1])
                             : "r"(baddr));
            }
#pragma unroll
            for (int nt = 0; nt < 8; nt++) mma_tf32(acc[nt], a, b[nt]);
        }
        CBAR();
    }
    // epilogue: write to Hout (global, ping-pong buffer)
    int row0 = cta * 64 + wm + (lane >> 2);
#pragma unroll
    for (int nt = 0; nt < 8; nt++) {
        int col = wn + nt * 8 + (lane & 3) * 2;
        *reinterpret_cast<float2*>(&Hout[(size_t)row0 * D + col]) =
            make_float2(acc[nt][0], acc[nt][1]);
        *reinterpret_cast<float2*>(&Hout[(size_t)(row0 + 8) * D + col]) =
            make_float2(acc[nt][2], acc[nt][3]);
    }
}

// ---------------- aggregate level l into smem As (or y for last level) -------
__device__ __forceinline__ void agg_to_smem(const int* __restrict__ ei,
                                            const float* __restrict__ bias,
                                            const float* __restrict__ x,
                                            const float* __restrict__ Hin,
                                            float* As, int l, const float* s_vsrc,
                                            float* red, int cta, int tid)
{
    const int warp = tid >> 5, lane = tid & 31;
    const float* asrc = g_asrc2[l & 1];
    float* anext = g_asrc2[(l + 1) & 1];
    const float4* H4 = (const float4*)Hin;
    const float4* b4 = (const float4*)bias;
    float ts = 0.f, tq = 0.f;
    const int lastlvl = (l == NLVL);

#pragma unroll 1
    for (int k = 0; k < 4; k++) {
        const int lr  = warp + k * 16;          // local row 0..63
        const int row = cta * 64 + lr;          // global dst row in level
        const int eb = (l - 1) * EPL + row * DEG;
        int sj[DEG]; float p[DEG];
        float ad = (l == 1) ? g_adst[row] : 0.f;
        float m = -1e30f;
#pragma unroll
        for (int j = 0; j < DEG; j++) {
            int s = ei[eb + j] - (l - 1) * PER;
            sj[j] = s;
            float a = asrc[s] + ad;
            a = a > 0.f ? a : 0.2f * a;           // leaky_relu 0.2
            p[j] = a;
            m = fmaxf(m, a);
        }
        float den = 0.f;
#pragma unroll
        for (int j = 0; j < DEG; j++) { p[j] = __expf(p[j] - m); den += p[j]; }
        float inv = 1.f / den;
#pragma unroll
        for (int j = 0; j < DEG; j++) p[j] *= inv;

        float4 a0 = b4[lane], a1 = b4[32 + lane];
#pragma unroll
        for (int j = 0; j < DEG; j++) {
            float4 h0 = H4[(size_t)sj[j] * 64 + lane];
            float4 h1 = H4[(size_t)sj[j] * 64 + 32 + lane];
            a0.x = fmaf(p[j], h0.x, a0.x); a0.y = fmaf(p[j], h0.y, a0.y);
            a0.z = fmaf(p[j], h0.z, a0.z); a0.w = fmaf(p[j], h0.w, a0.w);
            a1.x = fmaf(p[j], h1.x, a1.x); a1.y = fmaf(p[j], h1.y, a1.y);
            a1.z = fmaf(p[j], h1.z, a1.z); a1.w = fmaf(p[j], h1.w, a1.w);
        }
        if (!lastlvl) {
            // store to smem As with xor-by-row swizzle (16B seg granularity)
            int sw0 = (lane & ~7) | ((lane ^ lr) & 7);
            ((float4*)As)[lr * 64 + sw0]      = a0;
            ((float4*)As)[lr * 64 + 32 + sw0] = a1;
            const float4* v4 = (const float4*)s_vsrc;
            float4 v0 = v4[lane], v1 = v4[32 + lane];
            float d = a0.x * v0.x + a0.y * v0.y + a0.z * v0.z + a0.w * v0.w
                    + a1.x * v1.x + a1.y * v1.y + a1.z * v1.z + a1.w * v1.w;
#pragma unroll
            for (int o = 16; o > 0; o >>= 1) d += __shfl_xor_sync(0xffffffffu, d, o);
            if (lane == 0) anext[row] = d;
        } else {
            float4 x0 = ((const float4*)x)[(size_t)(7 * PER + row) * 64 + lane];
            float4 x1 = ((const float4*)x)[(size_t)(7 * PER + row) * 64 + 32 + lane];
            a0.x += x0.x; a0.y += x0.y; a0.z += x0.z; a0.w += x0.w;
            a1.x += x1.x; a1.y += x1.y; a1.z += x1.z; a1.w += x1.w;
            ((float4*)g_y)[(size_t)row * 64 + lane]      = a0;
            ((float4*)g_y)[(size_t)row * 64 + 32 + lane] = a1;
            ts += a0.x + a0.y + a0.z + a0.w + a1.x + a1.y + a1.z + a1.w;
            tq += a0.x * a0.x + a0.y * a0.y + a0.z * a0.z + a0.w * a0.w
                + a1.x * a1.x + a1.y * a1.y + a1.z * a1.z + a1.w * a1.w;
        }
    }
    if (lastlvl) {
#pragma unroll
        for (int o = 16; o > 0; o >>= 1) {
            ts += __shfl_xor_sync(0xffffffffu, ts, o);
            tq += __shfl_xor_sync(0xffffffffu, tq, o);
        }
        if (lane == 0) { red[warp] = ts; red[16 + warp] = tq; }
        CBAR();
        if (tid == 0) {
            float a = 0.f, b = 0.f;
#pragma unroll
            for (int j = 0; j < 16; j++) { a += red[j]; b += red[16 + j]; }
            g_psum[cta] += (double)a;
            g_psq[cta]  += (double)b;
        }
    }
}

// ---------------- the persistent kernel --------------------------------------
__global__ void __launch_bounds__(NTHR_TOT, 1) persist_kernel(
    const float* __restrict__ x, const int* __restrict__ ei,
    const float* __restrict__ W, const float* __restrict__ att_src,
    const float* __restrict__ att_dst, const float* __restrict__ bias,
    const float* __restrict__ gamma, const float* __restrict__ beta,
    float* __restrict__ out,
    const float4* __restrict__ esrc, float4* __restrict__ edst, long long ec4)
{
    __shared__ float s_vsrc[D];
    __shared__ float s_vdst[D];
    __shared__ float red[32];
    __shared__ float sbc[2];
    extern __shared__ float dyn[];
    float* As = dyn;                          // 64 x 256 (swizzled 16B segs)
    float* Bs = dyn + AS_BYTES / 4;           // 2 x 256 x 32 (swizzled)

    const int cta = blockIdx.x;
    const int tid = threadIdx.x;

    // ===== pure-copy CTAs (20 SMs, all 20 warps copying) ======================
    if (cta >= NCOMP) {
        if (esrc != nullptr) {
            long long gw = (long long)NCOMP * CWARPS
                         + (long long)(cta - NCOMP) * WARPS_TOT + (tid >> 5);
            copy_work(esrc, edst, ec4, gw);
        }
        return;
    }

    // ===== copy warps inside compute CTAs =====================================
    if (tid >= NTHR) {
        if (esrc != nullptr) {
            long long gw = (long long)cta * CWARPS + ((tid - NTHR) >> 5);
            copy_work(esrc, edst, ec4, gw);
        }
        return;
    }

    // ===== compute warps =======================================================
    const int warp = tid >> 5, lane = tid & 31;
    int ls = 1 ^ *((volatile int*)&g_sense);

    // P0: v-vectors (per-CTA smem), rowdots, stats over x head
    if (tid < D) {
        float s = 0.f, t = 0.f;
        for (int k = 0; k < D; k++) {
            float w2 = W[k * D + tid];
            s = fmaf(w2, att_src[k], s);
            t = fmaf(w2, att_dst[k], t);
        }
        s_vsrc[tid] = s;
        s_vdst[tid] = t;
    }
    CBAR();

    for (int idx = cta * 16 + warp; idx < 2 * PER; idx += NCOMP * 16) {
        const float* A; const float* v; int r;
        if (idx < PER) { r = idx;       A = x;                    v = s_vsrc; }
        else           { r = idx - PER; A = x + (size_t)PER * D;  v = s_vdst; }
        const float4* a4 = (const float4*)(A + (size_t)r * D);
        const float4* v4 = (const float4*)v;
        float s = 0.f;
#pragma unroll
        for (int i = 0; i < 2; i++) {
            float4 a  = a4[i * 32 + lane];
            float4 vv = v4[i * 32 + lane];
            s += a.x * vv.x + a.y * vv.y + a.z * vv.z + a.w * vv.w;
        }
#pragma unroll
        for (int o = 16; o > 0; o >>= 1) s += __shfl_xor_sync(0xffffffffu, s, o);
        if (lane == 0) { if (idx < PER) g_asrc2[1][r] = s; else g_adst[r] = s; }
    }

    {
        float s = 0.f, q = 0.f;
        const float4* x4 = (const float4*)x;
        const int total4 = (NNODES - PER) * (D / 4);
        for (int i = cta * NTHR + tid; i < total4; i += NCOMP * NTHR) {
            float4 v = x4[i];
            s += v.x + v.y + v.z + v.w;
            q += v.x * v.x + v.y * v.y + v.z * v.z + v.w * v.w;
        }
#pragma unroll
        for (int o = 16; o > 0; o >>= 1) {
            s += __shfl_xor_sync(0xffffffffu, s, o);
            q += __shfl_xor_sync(0xffffffffu, q, o);
        }
        if (lane == 0) { red[warp] = s; red[16 + warp] = q; }
        CBAR();
        if (tid == 0) {
            float a = 0.f, b = 0.f;
#pragma unroll
            for (int j = 0; j < 16; j++) { a += red[j]; b += red[16 + j]; }
            g_psum[cta] = (double)a;     // overwrite: no zero-init needed
            g_psq[cta]  = (double)b;
        }
    }
    // no gbar needed yet: next phase (load x -> As, gemm) is CTA-local until
    // the H write, and nothing reads H before the gbar after gemm.

    // ===== level-1 GEMM: As <- x[layer0] rows (this CTA's 64), gemm -> Ha =====
    {
#pragma unroll
        for (int k = 0; k < 4; k++) {
            int lr = warp + k * 16;
            const float4* xr = (const float4*)(x + (size_t)(cta * 64 + lr) * D);
            float4 a0 = xr[lane], a1 = xr[32 + lane];
            int sw0 = (lane & ~7) | ((lane ^ lr) & 7);
            ((float4*)As)[lr * 64 + sw0]      = a0;
            ((float4*)As)[lr * 64 + 32 + sw0] = a1;
        }
        CBAR();
        gemm_from_smem(As, Bs, W, g_Ha, cta, tid);
    }
    gbar(ls);   // H^1 complete everywhere (also covers P0 scalars)

    // ===== chain: one gbar per level ==========================================
    float* Hbuf[2];
    Hbuf[0] = g_Ha; Hbuf[1] = g_Hb;
#pragma unroll 1
    for (int l = 1; l < NLVL; l++) {
        const float* Hin = Hbuf[(l + 1) & 1];
        float* Hout = Hbuf[l & 1];
        agg_to_smem(ei, bias, x, Hin, As, l, s_vsrc, red, cta, tid);
        CBAR();                                  // As ready (CTA-local)
        gemm_from_smem(As, Bs, W, Hout, cta, tid);
        gbar(ls);                                // H^{l+1} complete everywhere
    }
    // level 7: aggregate to y + stats
    agg_to_smem(ei, bias, x, Hbuf[0], As, NLVL, s_vsrc, red, cta, tid);
    gbar(ls);   // stats complete everywhere

    // ===== norm ================================================================
    if (warp == 0) {
        double ds = 0.0, dq = 0.0;
        for (int i = lane; i < NCOMP; i += 32) { ds += g_psum[i]; dq += g_psq[i]; }
#pragma unroll
        for (int o = 16; o > 0; o >>= 1) {
            ds += __shfl_xor_sync(0xffffffffu, ds, o);
            dq += __shfl_xor_sync(0xffffffffu, dq, o);
        }
        if (lane == 0) {
            double cnt  = (double)NNODES * D;
            double mean = ds / cnt;
            double var  = dq / cnt - mean * mean;
            sbc[0] = (float)mean;
            sbc[1] = rsqrtf((float)var + 1e-5f);
        }
    }
    CBAR();
    const float mu = sbc[0], rstd = sbc[1];
    const int total4 = NNODES * (D / 4);
    const int tail4  = (NNODES - PER) * (D / 4);
    for (int i = cta * NTHR + tid; i < total4; i += NCOMP * NTHR) {
        float4 v = (i < tail4) ? ((const float4*)x)[i] : ((const float4*)g_y)[i - tail4];
        int c4 = i & 63;
        float4 g = ((const float4*)gamma)[c4];
        float4 b = ((const float4*)beta)[c4];
        float4 o;
        o.x = (v.x - mu) * rstd * g.x + b.x;
        o.y = (v.y - mu) * rstd * g.y + b.y;
        o.z = (v.z - mu) * rstd * g.z + b.z;
        o.w = (v.w - mu) * rstd * g.w + b.w;
        ((float4*)out)[i] = o;
    }
}

// ---------------- launch ----------------
extern "C" void kernel_launch(void* const* d_in, const int* in_sizes, int n_in,
                              void* d_out, int out_size) {
    const float* x       = (const float*)d_in[0];
    const int*   ei      = (const int*)d_in[1];
    const float* eattr   = (const float*)d_in[2];
    const float* W       = (const float*)d_in[5];
    const float* att_src = (const float*)d_in[6];
    const float* att_dst = (const float*)d_in[7];
    const float* bias    = (const float*)d_in[8];
    const float* gamma   = (const float*)d_in[9];
    const float* beta    = (const float*)d_in[10];
    float* out = (float*)d_out;

    static bool attr_set = false;
    if (!attr_set) {
        cudaFuncSetAttribute(persist_kernel,
                             cudaFuncAttributeMaxDynamicSharedMemorySize, DYN_SMEM);
        attr_set = true;
    }

    size_t eelems = (size_t)in_sizes[2];
    bool do_copy = ((size_t)out_size >= (size_t)NNODES * D + eelems);
    const float4* e4src = do_copy ? (const float4*)eattr : nullptr;
    float4* e4dst = do_copy ? (float4*)(out + (size_t)NNODES * D) : nullptr;
    long long ec4 = do_copy ? (long long)(eelems / 4) : 0;

    persist_kernel<<<NCTA, NTHR_TOT, DYN_SMEM>>>(x, ei, W, att_src, att_dst, bias,
                                                 gamma, beta, out, e4src, e4dst, ec4);
}